// round 11
// baseline (speedup 1.0000x reference)
#include <cuda_runtime.h>
#include <cuda_bf16.h>
#include <cstdint>

// Problem constants (fixed shapes)
#define N0    260000
#define N1    10240
#define BSZ   1024
#define E0    256000
#define E1    10240
#define IN_C  602
#define HID   256
#define OUT_C 41

#define KH    608      // padded half-K (602 + 6 zeros)
#define NCH   19       // K chunks of 32

// ---------------- scratch (static device memory; no allocation) ----------------
__device__ __align__(16) float g_acat2[(size_t)N1 * KH];   // 24.9 MB aggregated features (padded)
__device__ __align__(16) float g_p[(size_t)N1 * HID];      // 10.5 MB partial: x_tgt @ Wr^T
__device__ __align__(16) float g_bhl[(size_t)HID * KH];    // Wl^T hi
__device__ __align__(16) float g_bll[(size_t)HID * KH];    // Wl^T lo
__device__ __align__(16) float g_bhr[(size_t)HID * KH];    // Wr^T hi
__device__ __align__(16) float g_blr[(size_t)HID * KH];    // Wr^T lo
__device__ __align__(16) float g_h[(size_t)N1 * HID];      // layer-0 output (post ReLU)
__device__ __align__(16) float g_agg1[(size_t)BSZ * HID];
__device__ int g_seg0[N1 + 1];
__device__ int g_seg1[BSZ + 1];

// ---------------- helpers ----------------
__device__ __forceinline__ uint32_t smem_u32(const void* p) {
    uint32_t a;
    asm("{ .reg .u64 t; cvta.to.shared.u64 t, %1; cvt.u32.u64 %0, t; }" : "=r"(a) : "l"(p));
    return a;
}
__device__ __forceinline__ void split1(float v, float& h, float& l) {
    uint32_t hb; asm("cvt.rna.tf32.f32 %0, %1;" : "=r"(hb) : "f"(v));
    h = __uint_as_float(hb);
    float r = v - h;
    uint32_t lb; asm("cvt.rna.tf32.f32 %0, %1;" : "=r"(lb) : "f"(r));
    l = __uint_as_float(lb);
}
#define MMA_TF32(dd, aa, bb)                                                  \
    asm volatile("mma.sync.aligned.m16n8k8.row.col.f32.tf32.tf32.f32 "        \
        "{%0,%1,%2,%3}, {%4,%5,%6,%7}, {%8,%9}, {%0,%1,%2,%3};"               \
        : "+f"(dd[0]), "+f"(dd[1]), "+f"(dd[2]), "+f"(dd[3])                  \
        : "r"(aa[0]), "r"(aa[1]), "r"(aa[2]), "r"(aa[3]), "r"(bb[0]), "r"(bb[1]))
#define CP_ASYNC16(smem, gptr)                                                \
    asm volatile("cp.async.cg.shared.global [%0], [%1], 16;"                  \
        :: "r"(smem), "l"(gptr) : "memory")
#define CP_COMMIT() asm volatile("cp.async.commit_group;" ::: "memory")
#define CP_WAIT0()  asm volatile("cp.async.wait_group 0;" ::: "memory")
#define GBAR()      asm volatile("bar.sync 1, 128;" ::: "memory")

// ---------------- segment boundaries via binary search (dst is sorted) ----------------
__global__ void seg_kernel(const int* __restrict__ dst, int E, int Nt, int which) {
    int t = blockIdx.x * blockDim.x + threadIdx.x;
    if (t > Nt) return;
    int lo = 0, hi = E;
    while (lo < hi) {
        int mid = (lo + hi) >> 1;
        if (dst[mid] < t) lo = mid + 1; else hi = mid;
    }
    if (which == 0) g_seg0[t] = lo; else g_seg1[t] = lo;
}

// ---------------- B prep: transpose both weights into [n][k] hi/lo, zero-padded to KH ----------------
__global__ void __launch_bounds__(256) bprep_kernel(const float* __restrict__ Wl0,
                                                    const float* __restrict__ Wr0) {
    __shared__ float tlh[32][33], tll[32][33], trh[32][33], trl[32][33];
    int k0 = blockIdx.x * 32, n0 = blockIdx.y * 32;
    int tn = threadIdx.x & 31, tk = threadIdx.x >> 5;
#pragma unroll
    for (int i = 0; i < 4; i++) {
        int k = k0 + tk + i * 8;
        float wl = 0.f, wr = 0.f;
        if (k < IN_C) {
            wl = Wl0[(size_t)k * HID + n0 + tn];
            wr = Wr0[(size_t)k * HID + n0 + tn];
        }
        float h, l;
        split1(wl, h, l); tlh[tk + i * 8][tn] = h; tll[tk + i * 8][tn] = l;
        split1(wr, h, l); trh[tk + i * 8][tn] = h; trl[tk + i * 8][tn] = l;
    }
    __syncthreads();
    int wk = threadIdx.x & 31, wn = threadIdx.x >> 5;
#pragma unroll
    for (int i = 0; i < 4; i++) {
        int n = n0 + wn + i * 8;
        g_bhl[(size_t)n * KH + k0 + wk] = tlh[wk][wn + i * 8];
        g_bll[(size_t)n * KH + k0 + wk] = tll[wk][wn + i * 8];
        g_bhr[(size_t)n * KH + k0 + wk] = trh[wk][wn + i * 8];
        g_blr[(size_t)n * KH + k0 + wk] = trl[wk][wn + i * 8];
    }
}

// ---------------- fused kernel A: warps 0-3 GEMM (P = x_tgt @ Wr^T), warps 4-7 aggregation ----------------
// GEMM: CTA tile 128x32, 4 warps of 32x32, K=608 in 19 chunks of 32, double-buffered.
// Stage (floats): Ah[8][128*4]=4096 | Al=4096 | Bh[8][33*4]=1056 | Bl=1056  -> 10304
#define SSA 10304
__global__ void __launch_bounds__(256, 2) fusedA(const float* __restrict__ x,
                                                 const int* __restrict__ src) {
    extern __shared__ float sm[];
    int tid = threadIdx.x, lane = tid & 31, wid = tid >> 5;
    int bid = blockIdx.x;

    if (wid < 4) {
        // ============ GEMM role (128 threads, named barrier 1) ============
        int m0 = (bid % 80) * 128;
        int n0 = (bid / 80) * 32;
        int mw = wid * 32;
        int l4 = lane >> 2, lk = lane & 3;
        int gtid = tid;                         // 0..127
        uint32_t sb = smem_u32(sm);

        const float* xrow = x + (size_t)(m0 + gtid) * IN_C;
        int pn = gtid >> 2, pbj = gtid & 3;
        const float4* Bhg = (const float4*)(g_bhr + (size_t)(n0 + pn) * KH);
        const float4* Blg = (const float4*)(g_blr + (size_t)(n0 + pn) * KH);

        float2 ra2[16];
        float d[2][4][4] = {};

        auto ldgA = [&](int c) {
#pragma unroll
            for (int q = 0; q < 16; q++) {
                int kg = c * 32 + 2 * q;
                ra2[q] = (kg < IN_C) ? __ldg((const float2*)xrow + (kg >> 1))
                                     : make_float2(0.f, 0.f);
            }
        };
        auto stsA = [&](int st) {
            float4* Ah4 = (float4*)(sm + st * SSA);
            float4* Al4 = (float4*)(sm + st * SSA + 4096);
#pragma unroll
            for (int j = 0; j < 8; j++) {
                float4 h, l;
                split1(ra2[2 * j].x,     h.x, l.x);
                split1(ra2[2 * j].y,     h.y, l.y);
                split1(ra2[2 * j + 1].x, h.z, l.z);
                split1(ra2[2 * j + 1].y, h.w, l.w);
                Ah4[j * 128 + gtid] = h;
                Al4[j * 128 + gtid] = l;
            }
        };
        auto cpB = [&](int c, int st) {
            uint32_t bhb = sb + (st * SSA + 8192) * 4;
            uint32_t blb = sb + (st * SSA + 9248) * 4;
#pragma unroll
            for (int j = 0; j < 2; j++) {
                int k4 = pbj * 2 + j;
                uint32_t doff = (uint32_t)(k4 * 33 + pn) * 16;
                CP_ASYNC16(bhb + doff, &Bhg[c * 8 + k4]);
                CP_ASYNC16(blb + doff, &Blg[c * 8 + k4]);
            }
        };

        ldgA(0); cpB(0, 0); stsA(0);
        CP_COMMIT(); CP_WAIT0(); GBAR();

        for (int c = 0; c < NCH; c++) {
            int st = c & 1;
            if (c + 1 < NCH) { ldgA(c + 1); cpB(c + 1, st ^ 1); }
            const float* Ah = sm + st * SSA;
            const float* Al = Ah + 4096;
            const float* Bh = sm + st * SSA + 8192;
            const float* Bl = sm + st * SSA + 9248;
#pragma unroll
            for (int ks = 0; ks < 4; ks++) {
                uint32_t ah[2][4], al[2][4], bh[4][2], bl[4][2];
                int ab = 2 * ks * 512, bb = 2 * ks * 132;
#pragma unroll
                for (int mi = 0; mi < 2; mi++) {
                    int m = mw + mi * 16 + l4;
                    ah[mi][0] = __float_as_uint(Ah[ab + m * 4 + lk]);
                    ah[mi][1] = __float_as_uint(Ah[ab + (m + 8) * 4 + lk]);
                    ah[mi][2] = __float_as_uint(Ah[ab + 512 + m * 4 + lk]);
                    ah[mi][3] = __float_as_uint(Ah[ab + 512 + (m + 8) * 4 + lk]);
                    al[mi][0] = __float_as_uint(Al[ab + m * 4 + lk]);
                    al[mi][1] = __float_as_uint(Al[ab + (m + 8) * 4 + lk]);
                    al[mi][2] = __float_as_uint(Al[ab + 512 + m * 4 + lk]);
                    al[mi][3] = __float_as_uint(Al[ab + 512 + (m + 8) * 4 + lk]);
                }
#pragma unroll
                for (int ni = 0; ni < 4; ni++) {
                    int n = ni * 8 + l4;
                    bh[ni][0] = __float_as_uint(Bh[bb + n * 4 + lk]);
                    bh[ni][1] = __float_as_uint(Bh[bb + 132 + n * 4 + lk]);
                    bl[ni][0] = __float_as_uint(Bl[bb + n * 4 + lk]);
                    bl[ni][1] = __float_as_uint(Bl[bb + 132 + n * 4 + lk]);
                }
#pragma unroll
                for (int mi = 0; mi < 2; mi++)
#pragma unroll
                    for (int ni = 0; ni < 4; ni++) {
                        MMA_TF32(d[mi][ni], ah[mi], bh[ni]);   // hi*hi
                        MMA_TF32(d[mi][ni], al[mi], bh[ni]);   // lo*hi
                        MMA_TF32(d[mi][ni], ah[mi], bl[ni]);   // hi*lo
                    }
            }
            if (c + 1 < NCH) {
                stsA(st ^ 1);
                CP_COMMIT(); CP_WAIT0(); GBAR();
            }
        }
        // epilogue: raw partial -> g_p
#pragma unroll
        for (int mi = 0; mi < 2; mi++) {
            int m = m0 + mw + mi * 16 + l4;
#pragma unroll
            for (int ni = 0; ni < 4; ni++) {
                int n = n0 + ni * 8 + 2 * lk;
                *(float2*)&g_p[(size_t)m * HID + n] = make_float2(d[mi][ni][0], d[mi][ni][1]);
                *(float2*)&g_p[(size_t)(m + 8) * HID + n] = make_float2(d[mi][ni][2], d[mi][ni][3]);
            }
        }
    } else {
        // ============ AGG role (warp-per-node, 4 nodes per warp) ============
        int aw = wid - 4;
        for (int j = 0; j < 4; j++) {
            int t = bid * 16 + aw * 4 + j;
            int s = g_seg0[t], e = g_seg0[t + 1];
            float2 acc[10];
#pragma unroll
            for (int r = 0; r < 10; r++) acc[r] = make_float2(0.f, 0.f);
            int i = s;
            for (; i + 1 < e; i += 2) {
                const float2* r0 = (const float2*)(x + (size_t)__ldg(src + i) * IN_C);
                const float2* r1 = (const float2*)(x + (size_t)__ldg(src + i + 1) * IN_C);
                float2 v0[10], v1[10];
#pragma unroll
                for (int r = 0; r < 10; r++) {
                    int f = lane + 32 * r;
                    if (f < 301) { v0[r] = __ldg(r0 + f); v1[r] = __ldg(r1 + f); }
                }
#pragma unroll
                for (int r = 0; r < 10; r++) {
                    int f = lane + 32 * r;
                    if (f < 301) {
                        acc[r].x += v0[r].x + v1[r].x;
                        acc[r].y += v0[r].y + v1[r].y;
                    }
                }
            }
            if (i < e) {
                const float2* r0 = (const float2*)(x + (size_t)__ldg(src + i) * IN_C);
#pragma unroll
                for (int r = 0; r < 10; r++) {
                    int f = lane + 32 * r;
                    if (f < 301) {
                        float2 v = __ldg(r0 + f);
                        acc[r].x += v.x; acc[r].y += v.y;
                    }
                }
            }
            float inv = (e > s) ? 1.f / (float)(e - s) : 1.f;
            float2* dr = (float2*)(g_acat2 + (size_t)t * KH);
#pragma unroll
            for (int r = 0; r < 10; r++) {
                int f = lane + 32 * r;
                if (f < 301) dr[f] = make_float2(acc[r].x * inv, acc[r].y * inv);
            }
            if (lane < 3) dr[301 + lane] = make_float2(0.f, 0.f);
        }
    }
}

// ---------------- kernel B: h = relu(agg @ Wl^T + P + bias) ----------------
// CTA 128x64, BK=32, 8 warps (32x32 each), double-buffered, 3xTF32 (R8-proven pipeline).
// Stage (floats): Ah 4096 | Al 4096 | Bh[8][65*4]=2080 | Bl 2080 -> 12352
#define SSB 12352
__global__ void __launch_bounds__(256, 2) gemmB(const float* __restrict__ bias) {
    extern __shared__ float sm[];
    uint32_t sb = smem_u32(sm);
    int tid = threadIdx.x;
    int lane = tid & 31, wid = tid >> 5;
    int mw = (wid >> 1) * 32, nw = (wid & 1) * 32;
    int l4 = lane >> 2, lk = lane & 3;
    int m0 = blockIdx.x * 128, n0 = blockIdx.y * 64;

    int pm = tid >> 1;
    int pk4 = (tid & 1) * 4;
    const float4* Ag = (const float4*)(g_acat2 + (size_t)(m0 + pm) * KH);
    int pn = tid >> 2;
    int pb4 = (tid & 3) * 2;
    const float4* Bhg = (const float4*)(g_bhl + (size_t)(n0 + pn) * KH);
    const float4* Blg = (const float4*)(g_bll + (size_t)(n0 + pn) * KH);

    float4 ra[4];

#define LDG_A(c)                                                            \
    {                                                                       \
        _Pragma("unroll")                                                   \
        for (int j = 0; j < 4; j++) ra[j] = __ldg(&Ag[(c) * 8 + pk4 + j]);  \
    }
#define STS_A(st)                                                           \
    {                                                                       \
        float4* Ah4 = (float4*)(sm + (st) * SSB);                           \
        float4* Al4 = (float4*)(sm + (st) * SSB + 4096);                    \
        _Pragma("unroll")                                                   \
        for (int j = 0; j < 4; j++) {                                       \
            float4 h, l;                                                    \
            split1(ra[j].x, h.x, l.x); split1(ra[j].y, h.y, l.y);           \
            split1(ra[j].z, h.z, l.z); split1(ra[j].w, h.w, l.w);           \
            Ah4[(pk4 + j) * 128 + pm] = h;                                  \
            Al4[(pk4 + j) * 128 + pm] = l;                                  \
        }                                                                   \
    }
#define CP_B(c, st)                                                         \
    {                                                                       \
        uint32_t bhb = sb + ((st) * SSB + 8192) * 4;                        \
        uint32_t blb = sb + ((st) * SSB + 10272) * 4;                       \
        _Pragma("unroll")                                                   \
        for (int j = 0; j < 2; j++) {                                       \
            int k4 = pb4 + j;                                               \
            uint32_t doff = (uint32_t)(k4 * 65 + pn) * 16;                  \
            CP_ASYNC16(bhb + doff, &Bhg[(c) * 8 + k4]);                     \
            CP_ASYNC16(blb + doff, &Blg[(c) * 8 + k4]);                     \
        }                                                                   \
    }

    LDG_A(0); CP_B(0, 0); STS_A(0);
    CP_COMMIT(); CP_WAIT0();
    __syncthreads();

    float d[2][4][4] = {};

    for (int c = 0; c < NCH; c++) {
        int st = c & 1;
        if (c + 1 < NCH) { LDG_A(c + 1); CP_B(c + 1, st ^ 1); }

        const float* Ah = sm + st * SSB;
        const float* Al = Ah + 4096;
        const float* Bh = sm + st * SSB + 8192;
        const float* Bl = sm + st * SSB + 10272;

#pragma unroll
        for (int ks = 0; ks < 4; ks++) {
            uint32_t ah[2][4], al[2][4], bhf[4][2], blf[4][2];
            int abase = 2 * ks * 512;
            int bbase = 2 * ks * 260;
#pragma unroll
            for (int mi = 0; mi < 2; mi++) {
                int m = mw + mi * 16 + l4;
                ah[mi][0] = __float_as_uint(Ah[abase + m * 4 + lk]);
                ah[mi][1] = __float_as_uint(Ah[abase + (m + 8) * 4 + lk]);
                ah[mi][2] = __float_as_uint(Ah[abase + 512 + m * 4 + lk]);
                ah[mi][3] = __float_as_uint(Ah[abase + 512 + (m + 8) * 4 + lk]);
                al[mi][0] = __float_as_uint(Al[abase + m * 4 + lk]);
                al[mi][1] = __float_as_uint(Al[abase + (m + 8) * 4 + lk]);
                al[mi][2] = __float_as_uint(Al[abase + 512 + m * 4 + lk]);
                al[mi][3] = __float_as_uint(Al[abase + 512 + (m + 8) * 4 + lk]);
            }
#pragma unroll
            for (int ni = 0; ni < 4; ni++) {
                int n = nw + ni * 8 + l4;
                bhf[ni][0] = __float_as_uint(Bh[bbase + n * 4 + lk]);
                bhf[ni][1] = __float_as_uint(Bh[bbase + 260 + n * 4 + lk]);
                blf[ni][0] = __float_as_uint(Bl[bbase + n * 4 + lk]);
                blf[ni][1] = __float_as_uint(Bl[bbase + 260 + n * 4 + lk]);
            }
#pragma unroll
            for (int mi = 0; mi < 2; mi++)
#pragma unroll
                for (int ni = 0; ni < 4; ni++) {
                    MMA_TF32(d[mi][ni], ah[mi], bhf[ni]);
                    MMA_TF32(d[mi][ni], al[mi], bhf[ni]);
                    MMA_TF32(d[mi][ni], ah[mi], blf[ni]);
                }
        }

        if (c + 1 < NCH) {
            STS_A(st ^ 1);
            CP_COMMIT(); CP_WAIT0();
            __syncthreads();
        }
    }

    // epilogue: + P + bias, relu
#pragma unroll
    for (int mi = 0; mi < 2; mi++) {
        int m = m0 + mw + mi * 16 + l4;
#pragma unroll
        for (int ni = 0; ni < 4; ni++) {
            int n = n0 + nw + ni * 8 + 2 * lk;
            float b0 = __ldg(&bias[n]), b1 = __ldg(&bias[n + 1]);
            float2 p0 = __ldg((const float2*)&g_p[(size_t)m * HID + n]);
            float2 p1 = __ldg((const float2*)&g_p[(size_t)(m + 8) * HID + n]);
            *(float2*)&g_h[(size_t)m * HID + n] =
                make_float2(fmaxf(d[mi][ni][0] + p0.x + b0, 0.f),
                            fmaxf(d[mi][ni][1] + p0.y + b1, 0.f));
            *(float2*)&g_h[(size_t)(m + 8) * HID + n] =
                make_float2(fmaxf(d[mi][ni][2] + p1.x + b0, 0.f),
                            fmaxf(d[mi][ni][3] + p1.y + b1, 0.f));
        }
    }
}

// ---------------- layer-1 mean aggregation ----------------
__global__ void __launch_bounds__(256) agg1_kernel(const int* __restrict__ src) {
    int t = blockIdx.x;
    int tid = threadIdx.x;
    int s = g_seg1[t], e = g_seg1[t + 1];
    __shared__ int sidx[256];
    float a = 0.f;
    for (int base = s; base < e; base += 256) {
        int n = min(256, e - base);
        if (tid < n) sidx[tid] = src[base + tid];
        __syncthreads();
#pragma unroll 4
        for (int i = 0; i < n; i++)
            a += g_h[(size_t)sidx[i] * HID + tid];
        __syncthreads();
    }
    float inv = (e > s) ? (1.0f / (float)(e - s)) : 1.0f;
    g_agg1[(size_t)t * HID + tid] = a * inv;
}

// ---------------- layer-1 GEMM + log_softmax, one CTA per output row ----------------
__global__ void __launch_bounds__(256) out_kernel(const float* __restrict__ Wl1,
                                                  const float* __restrict__ Wr1,
                                                  const float* __restrict__ bl1,
                                                  float* __restrict__ out) {
    int t = blockIdx.x;
    int tid = threadIdx.x;
    __shared__ float av[2 * HID];
    __shared__ float logits[48];

    av[tid]       = g_agg1[(size_t)t * HID + tid];
    av[HID + tid] = g_h[(size_t)t * HID + tid];
    __syncthreads();

    int c = tid >> 2; if (c > OUT_C - 1) c = OUT_C - 1;
    int p = tid & 3;
    const float* W = (p < 2) ? Wl1 : Wr1;
    int kbase = p * 128;
    int wbase = (p < 2) ? (kbase * OUT_C) : ((kbase - HID) * OUT_C);
    float s0 = 0.f, s1 = 0.f;
#pragma unroll 8
    for (int k = 0; k < 128; k += 2) {
        s0 += av[kbase + k]     * __ldg(&W[wbase + k * OUT_C + c]);
        s1 += av[kbase + k + 1] * __ldg(&W[wbase + (k + 1) * OUT_C + c]);
    }
    float s = s0 + s1;
    s += __shfl_xor_sync(0xffffffffu, s, 1);
    s += __shfl_xor_sync(0xffffffffu, s, 2);
    if (p == 0 && (tid >> 2) < OUT_C) logits[tid >> 2] = s + bl1[tid >> 2];
    __syncthreads();

    if (tid < 32) {
        float v0 = logits[tid];
        bool hi = (tid + 32) < OUT_C;
        float v1 = hi ? logits[tid + 32] : -3.4e38f;
        float mx = fmaxf(v0, v1);
#pragma unroll
        for (int o = 16; o > 0; o >>= 1)
            mx = fmaxf(mx, __shfl_xor_sync(0xffffffffu, mx, o));
        float es = expf(v0 - mx) + (hi ? expf(v1 - mx) : 0.f);
#pragma unroll
        for (int o = 16; o > 0; o >>= 1)
            es += __shfl_xor_sync(0xffffffffu, es, o);
        float lse = logf(es) + mx;
        out[(size_t)t * OUT_C + tid] = v0 - lse;
        if (hi) out[(size_t)t * OUT_C + tid + 32] = v1 - lse;
    }
}

// ---------------- launch ----------------
extern "C" void kernel_launch(void* const* d_in, const int* in_sizes, int n_in,
                              void* d_out, int out_size) {
    const float* x    = (const float*)d_in[0];
    const float* Wl0  = (const float*)d_in[1];
    const float* bl0  = (const float*)d_in[2];
    const float* Wr0  = (const float*)d_in[3];
    const float* Wl1  = (const float*)d_in[4];
    const float* bl1  = (const float*)d_in[5];
    const float* Wr1  = (const float*)d_in[6];
    const int*   src0 = (const int*)d_in[7];
    const int*   dst0 = (const int*)d_in[8];
    const int*   src1 = (const int*)d_in[9];
    const int*   dst1 = (const int*)d_in[10];
    float* out = (float*)d_out;

    const int smemA = 2 * SSA * 4;   // 82432
    const int smemB = 2 * SSB * 4;   // 98816
    cudaFuncSetAttribute(fusedA, cudaFuncAttributeMaxDynamicSharedMemorySize, smemA);
    cudaFuncSetAttribute(gemmB,  cudaFuncAttributeMaxDynamicSharedMemorySize, smemB);

    seg_kernel<<<(N1 + 1 + 255) / 256, 256>>>(dst0, E0, N1, 0);
    seg_kernel<<<(BSZ + 1 + 255) / 256, 256>>>(dst1, E1, BSZ, 1);

    bprep_kernel<<<dim3(KH / 32, HID / 32), 256>>>(Wl0, Wr0);

    // layer 0: fused (x_tgt GEMM || aggregation), then dependent GEMM
    fusedA<<<640, 256, smemA>>>(x, src0);
    gemmB<<<dim3(N1 / 128, HID / 64), 256, smemB>>>(bl0);

    // layer 1
    agg1_kernel<<<BSZ, 256>>>(src1);
    out_kernel<<<BSZ, 256>>>(Wl1, Wr1, bl1, out);
}

// round 16
// speedup vs baseline: 1.4240x; 1.4240x over previous
#include <cuda_runtime.h>
#include <cuda_bf16.h>
#include <cstdint>

// Problem constants (fixed shapes)
#define N0    260000
#define N1    10240
#define BSZ   1024
#define E0    256000
#define E1    10240
#define IN_C  602
#define HID   256
#define OUT_C 41

// Concat-K layout: [0,602)=agg, [602,608)=0, [608,1210)=x_tgt, [1210,1216)=0
#define KCAT  1216
#define KU    608      // KCAT in uint32 (bf16 pairs)
#define NST   38       // K stages of 32

// ---------------- scratch (static device memory; no allocation) ----------------
// A in bf16 hi/lo (written by agg0): [N1][608] uint32 (bf16x2), row = 2432 B
__device__ __align__(16) uint32_t g_ah[(size_t)N1 * KU];   // 24.9 MB
__device__ __align__(16) uint32_t g_al[(size_t)N1 * KU];   // 24.9 MB
// B^T in bf16 hi/lo: [HID][608] uint32
__device__ __align__(16) uint32_t g_bh[(size_t)HID * KU];  // 622 KB
__device__ __align__(16) uint32_t g_bl[(size_t)HID * KU];  // 622 KB
__device__ __align__(16) float g_h[(size_t)N1 * HID];      // 10.5 MB layer-0 out (post ReLU)
__device__ __align__(16) float g_agg1[(size_t)BSZ * HID];
__device__ int g_seg0[N1 + 1];
__device__ int g_seg1[BSZ + 1];

// ---------------- helpers ----------------
__device__ __forceinline__ uint32_t smem_u32(const void* p) {
    uint32_t a;
    asm("{ .reg .u64 t; cvta.to.shared.u64 t, %1; cvt.u32.u64 %0, t; }" : "=r"(a) : "l"(p));
    return a;
}
// pack float2 -> bf16x2 hi + bf16x2 lo (residual)
__device__ __forceinline__ uint32_t pack_hl(float2 v, uint32_t& lo) {
    __nv_bfloat16 hx = __float2bfloat16(v.x);
    __nv_bfloat16 hy = __float2bfloat16(v.y);
    float rx = v.x - __bfloat162float(hx);
    float ry = v.y - __bfloat162float(hy);
    __nv_bfloat16 lx = __float2bfloat16(rx);
    __nv_bfloat16 ly = __float2bfloat16(ry);
    lo = ((uint32_t)__bfloat16_as_ushort(ly) << 16) | __bfloat16_as_ushort(lx);
    return ((uint32_t)__bfloat16_as_ushort(hy) << 16) | __bfloat16_as_ushort(hx);
}
#define MMA_BF16(dd, aa, b0, b1)                                               \
    asm volatile("mma.sync.aligned.m16n8k16.row.col.f32.bf16.bf16.f32 "        \
        "{%0,%1,%2,%3}, {%4,%5,%6,%7}, {%8,%9}, {%0,%1,%2,%3};"                \
        : "+f"(dd[0]), "+f"(dd[1]), "+f"(dd[2]), "+f"(dd[3])                   \
        : "r"(aa[0]), "r"(aa[1]), "r"(aa[2]), "r"(aa[3]), "r"(b0), "r"(b1))
#define LDSM4(r0, r1, r2, r3, a)                                               \
    asm volatile("ldmatrix.sync.aligned.m8n8.x4.shared.b16 {%0,%1,%2,%3}, [%4];" \
        : "=r"(r0), "=r"(r1), "=r"(r2), "=r"(r3) : "r"(a))
#define CP_ASYNC16(smem, gptr)                                                 \
    asm volatile("cp.async.cg.shared.global [%0], [%1], 16;"                   \
        :: "r"(smem), "l"(gptr) : "memory")
#define CP_COMMIT() asm volatile("cp.async.commit_group;" ::: "memory")
#define CP_WAIT0()  asm volatile("cp.async.wait_group 0;" ::: "memory")

// ---------------- segment boundaries via binary search (dst is sorted) ----------------
__global__ void seg_kernel(const int* __restrict__ dst, int E, int Nt, int which) {
    int t = blockIdx.x * blockDim.x + threadIdx.x;
    if (t > Nt) return;
    int lo = 0, hi = E;
    while (lo < hi) {
        int mid = (lo + hi) >> 1;
        if (dst[mid] < t) lo = mid + 1; else hi = mid;
    }
    if (which == 0) g_seg0[t] = lo; else g_seg1[t] = lo;
}

// ---------------- B prep: transpose concat weight into [n][k], split bf16 hi/lo ----------------
// grid (38, 8): k-tile 32 x n-tile 32
__global__ void __launch_bounds__(256) bprep_kernel(const float* __restrict__ Wl0,
                                                    const float* __restrict__ Wr0) {
    __shared__ float tw[32][33];
    int k0 = blockIdx.x * 32, n0 = blockIdx.y * 32;
    int tn = threadIdx.x & 31, tk = threadIdx.x >> 5;
#pragma unroll
    for (int i = 0; i < 4; i++) {
        int k = k0 + tk + i * 8;
        float w = 0.f;
        if (k < IN_C)                  w = Wl0[(size_t)k * HID + n0 + tn];
        else if (k >= 608 && k < 1210) w = Wr0[(size_t)(k - 608) * HID + n0 + tn];
        tw[tk + i * 8][tn] = w;
    }
    __syncthreads();
    // write: 32 n-rows x 16 uint32 (2 k each) = 512, 2 per thread
#pragma unroll
    for (int t = 0; t < 2; t++) {
        int u = threadIdx.x + t * 256;
        int n = u >> 4, k2 = u & 15;
        float2 v = make_float2(tw[2 * k2][n], tw[2 * k2 + 1][n]);
        uint32_t lo, hi = pack_hl(v, lo);
        size_t idx = (size_t)(n0 + n) * KU + (k0 >> 1) + k2;
        g_bh[idx] = hi;
        g_bl[idx] = lo;
    }
}

// ---------------- layer-0 mean aggregation + x_tgt copy -> bf16 hi/lo A rows ----------------
__global__ void __launch_bounds__(256) agg0_kernel(const float* __restrict__ x,
                                                   const int* __restrict__ src) {
    int t = blockIdx.x;
    int tid = threadIdx.x;
    int s = g_seg0[t], e = g_seg0[t + 1];
    __shared__ int sidx[256];

    float2 a01 = {0.f, 0.f}, a23 = {0.f, 0.f};
    for (int base = s; base < e; base += 256) {
        int n = min(256, e - base);
        if (tid < n) sidx[tid] = src[base + tid];
        __syncthreads();
#pragma unroll 4
        for (int i = 0; i < n; i++) {
            const float2* row = (const float2*)(x + (size_t)sidx[i] * IN_C);
            float2 v = __ldg(&row[tid]);
            a01.x += v.x; a01.y += v.y;
            if (tid < 45) {
                float2 w = __ldg(&row[256 + tid]);
                a23.x += w.x; a23.y += w.y;
            }
        }
        __syncthreads();
    }
    float inv = (e > s) ? (1.0f / (float)(e - s)) : 1.0f;
    uint32_t* dh = g_ah + (size_t)t * KU;
    uint32_t* dl = g_al + (size_t)t * KU;

    uint32_t lo, hi;
    hi = pack_hl(make_float2(a01.x * inv, a01.y * inv), lo);
    dh[tid] = hi; dl[tid] = lo;
    if (tid < 45) {
        hi = pack_hl(make_float2(a23.x * inv, a23.y * inv), lo);
        dh[256 + tid] = hi; dl[256 + tid] = lo;
    }
    if (tid < 3) {
        dh[301 + tid] = 0u; dl[301 + tid] = 0u;      // cols 602..607
        dh[605 + tid] = 0u; dl[605 + tid] = 0u;      // cols 1210..1215
    }
    // x_tgt (first N1 rows of x) -> cols [608,1210)
    const float2* xr = (const float2*)(x + (size_t)t * IN_C);
    hi = pack_hl(__ldg(&xr[tid]), lo);
    dh[304 + tid] = hi; dl[304 + tid] = lo;
    if (tid < 45) {
        hi = pack_hl(__ldg(&xr[256 + tid]), lo);
        dh[560 + tid] = hi; dl[560 + tid] = lo;
    }
}

// ---------------- layer-0 GEMM: h = relu(A @ B^T + bias), bf16 3-term split ----------------
// CTA 128x64, BK=32, 8 warps (warp tile 32x32), double-buffered cp.async, ldmatrix.x4.
// SMEM stage (bytes): Ah 128*80=10240 @0 | Al @10240 | Bh 64*80=5120 @20480 | Bl @25600. stride 30720.
#define STG 30720
__global__ void __launch_bounds__(256, 2) gemm0_bf16(const float* __restrict__ bias) {
    extern __shared__ char sm[];
    uint32_t sb = smem_u32(sm);
    int tid = threadIdx.x, lane = tid & 31, wid = tid >> 5;
    int m0 = blockIdx.x * 128, n0 = blockIdx.y * 64;
    int mw = (wid >> 1) * 32, nw = (wid & 1) * 32;
    int l4 = lane >> 2, lk = lane & 3;

    // ldmatrix lane-dependent offsets (80 B padded rows -> conflict-free)
    int g = lane >> 3, r = lane & 7;
    uint32_t offA = (uint32_t)(mw + (g & 1) * 8 + r) * 80 + (g >> 1) * 16;
    uint32_t offB = (uint32_t)(nw + (g >> 1) * 8 + r) * 80 + (g & 1) * 16;

    auto loadst = [&](int c, int st) {
        uint32_t sbase = sb + st * STG;
#pragma unroll
        for (int t = 0; t < 4; t++) {
            int u = tid + t * 256;
            int half = u >> 9, v = u & 511, row = v >> 2, ch = v & 3;
            const char* srcp = (const char*)(half ? g_al : g_ah)
                             + (size_t)(m0 + row) * 2432 + c * 64 + ch * 16;
            CP_ASYNC16(sbase + half * 10240 + row * 80 + ch * 16, srcp);
        }
#pragma unroll
        for (int t = 0; t < 2; t++) {
            int u = tid + t * 256;
            int half = u >> 8, v = u & 255, row = v >> 2, ch = v & 3;
            const char* srcp = (const char*)(half ? g_bl : g_bh)
                             + (size_t)(n0 + row) * 2432 + c * 64 + ch * 16;
            CP_ASYNC16(sbase + 20480 + half * 5120 + row * 80 + ch * 16, srcp);
        }
    };

    float d[2][4][4] = {};

    loadst(0, 0);
    CP_COMMIT();

    for (int c = 0; c < NST; c++) {
        int st = c & 1;
        CP_WAIT0();
        __syncthreads();
        if (c + 1 < NST) { loadst(c + 1, st ^ 1); CP_COMMIT(); }

        uint32_t sbase = sb + st * STG;
#pragma unroll
        for (int ks = 0; ks < 2; ks++) {
            uint32_t ah[2][4], al[2][4], bh[2][4], bl[2][4];
            uint32_t aA = sbase + ks * 32 + offA;
            uint32_t aB = sbase + 20480 + ks * 32 + offB;
#pragma unroll
            for (int mi = 0; mi < 2; mi++) {
                LDSM4(ah[mi][0], ah[mi][1], ah[mi][2], ah[mi][3], aA + mi * 1280);
                LDSM4(al[mi][0], al[mi][1], al[mi][2], al[mi][3], aA + 10240 + mi * 1280);
            }
#pragma unroll
            for (int p = 0; p < 2; p++) {
                LDSM4(bh[p][0], bh[p][1], bh[p][2], bh[p][3], aB + p * 1280);
                LDSM4(bl[p][0], bl[p][1], bl[p][2], bl[p][3], aB + 5120 + p * 1280);
            }
#pragma unroll
            for (int mi = 0; mi < 2; mi++)
#pragma unroll
                for (int p = 0; p < 2; p++)
#pragma unroll
                    for (int q = 0; q < 2; q++) {
                        float* acc = d[mi][2 * p + q];
                        MMA_BF16(acc, ah[mi], bh[p][2 * q], bh[p][2 * q + 1]);  // hi*hi
                        MMA_BF16(acc, al[mi], bh[p][2 * q], bh[p][2 * q + 1]);  // lo*hi
                        MMA_BF16(acc, ah[mi], bl[p][2 * q], bl[p][2 * q + 1]);  // hi*lo
                    }
        }
    }

    // epilogue: bias + relu
#pragma unroll
    for (int mi = 0; mi < 2; mi++) {
        int m = m0 + mw + mi * 16 + l4;
#pragma unroll
        for (int ni = 0; ni < 4; ni++) {
            int n = n0 + nw + ni * 8 + 2 * lk;
            float b0 = __ldg(&bias[n]), b1 = __ldg(&bias[n + 1]);
            *(float2*)&g_h[(size_t)m * HID + n] =
                make_float2(fmaxf(d[mi][ni][0] + b0, 0.f),
                            fmaxf(d[mi][ni][1] + b1, 0.f));
            *(float2*)&g_h[(size_t)(m + 8) * HID + n] =
                make_float2(fmaxf(d[mi][ni][2] + b0, 0.f),
                            fmaxf(d[mi][ni][3] + b1, 0.f));
        }
    }
}

// ---------------- layer-1 mean aggregation ----------------
__global__ void __launch_bounds__(256) agg1_kernel(const int* __restrict__ src) {
    int t = blockIdx.x;
    int tid = threadIdx.x;
    int s = g_seg1[t], e = g_seg1[t + 1];
    __shared__ int sidx[256];
    float a = 0.f;
    for (int base = s; base < e; base += 256) {
        int n = min(256, e - base);
        if (tid < n) sidx[tid] = src[base + tid];
        __syncthreads();
#pragma unroll 4
        for (int i = 0; i < n; i++)
            a += g_h[(size_t)sidx[i] * HID + tid];
        __syncthreads();
    }
    float inv = (e > s) ? (1.0f / (float)(e - s)) : 1.0f;
    g_agg1[(size_t)t * HID + tid] = a * inv;
}

// ---------------- layer-1 GEMM + log_softmax, one CTA per output row ----------------
__global__ void __launch_bounds__(256) out_kernel(const float* __restrict__ Wl1,
                                                  const float* __restrict__ Wr1,
                                                  const float* __restrict__ bl1,
                                                  float* __restrict__ out) {
    int t = blockIdx.x;
    int tid = threadIdx.x;
    __shared__ float av[2 * HID];
    __shared__ float logits[48];

    av[tid]       = g_agg1[(size_t)t * HID + tid];
    av[HID + tid] = g_h[(size_t)t * HID + tid];
    __syncthreads();

    int c = tid >> 2; if (c > OUT_C - 1) c = OUT_C - 1;
    int p = tid & 3;
    const float* W = (p < 2) ? Wl1 : Wr1;
    int kbase = p * 128;
    int wbase = (p < 2) ? (kbase * OUT_C) : ((kbase - HID) * OUT_C);
    float s0 = 0.f, s1 = 0.f;
#pragma unroll 8
    for (int k = 0; k < 128; k += 2) {
        s0 += av[kbase + k]     * __ldg(&W[wbase + k * OUT_C + c]);
        s1 += av[kbase + k + 1] * __ldg(&W[wbase + (k + 1) * OUT_C + c]);
    }
    float s = s0 + s1;
    s += __shfl_xor_sync(0xffffffffu, s, 1);
    s += __shfl_xor_sync(0xffffffffu, s, 2);
    if (p == 0 && (tid >> 2) < OUT_C) logits[tid >> 2] = s + bl1[tid >> 2];
    __syncthreads();

    if (tid < 32) {
        float v0 = logits[tid];
        bool hi = (tid + 32) < OUT_C;
        float v1 = hi ? logits[tid + 32] : -3.4e38f;
        float mx = fmaxf(v0, v1);
#pragma unroll
        for (int o = 16; o > 0; o >>= 1)
            mx = fmaxf(mx, __shfl_xor_sync(0xffffffffu, mx, o));
        float es = expf(v0 - mx) + (hi ? expf(v1 - mx) : 0.f);
#pragma unroll
        for (int o = 16; o > 0; o >>= 1)
            es += __shfl_xor_sync(0xffffffffu, es, o);
        float lse = logf(es) + mx;
        out[(size_t)t * OUT_C + tid] = v0 - lse;
        if (hi) out[(size_t)t * OUT_C + tid + 32] = v1 - lse;
    }
}

// ---------------- launch ----------------
extern "C" void kernel_launch(void* const* d_in, const int* in_sizes, int n_in,
                              void* d_out, int out_size) {
    const float* x    = (const float*)d_in[0];
    const float* Wl0  = (const float*)d_in[1];
    const float* bl0  = (const float*)d_in[2];
    const float* Wr0  = (const float*)d_in[3];
    const float* Wl1  = (const float*)d_in[4];
    const float* bl1  = (const float*)d_in[5];
    const float* Wr1  = (const float*)d_in[6];
    const int*   src0 = (const int*)d_in[7];
    const int*   dst0 = (const int*)d_in[8];
    const int*   src1 = (const int*)d_in[9];
    const int*   dst1 = (const int*)d_in[10];
    float* out = (float*)d_out;

    const int smem_bytes = 2 * STG;   // 61440
    cudaFuncSetAttribute(gemm0_bf16, cudaFuncAttributeMaxDynamicSharedMemorySize, smem_bytes);

    seg_kernel<<<(N1 + 1 + 255) / 256, 256>>>(dst0, E0, N1, 0);
    seg_kernel<<<(BSZ + 1 + 255) / 256, 256>>>(dst1, E1, BSZ, 1);

    bprep_kernel<<<dim3(NST, HID / 32), 256>>>(Wl0, Wr0);

    // layer 0
    agg0_kernel<<<N1, 256>>>(x, src0);
    gemm0_bf16<<<dim3(N1 / 128, HID / 64), 256, smem_bytes>>>(bl0);

    // layer 1
    agg1_kernel<<<BSZ, 256>>>(src1);
    out_kernel<<<BSZ, 256>>>(Wl1, Wr1, bl1, out);
}